// round 11
// baseline (speedup 1.0000x reference)
#include <cuda_runtime.h>
#include <cuda_fp16.h>
#include <cstdint>

#define BQ   65536
#define HID  256
#define NCOL 2695
#define NPAD 2816                 // 22 * 128
#define TILE_B  16384             // 128 rows x 128B (64 fp16 of k), SW128-swizzled
#define STAGE_B (3 * TILE_B)      // A, Bhi, Blo = 48 KB
#define NSTAGE  2
#define DYN_BYTES (NSTAGE * STAGE_B)   // 96 KB

typedef __half fp16;

// ---------------- scratch ----------------
__device__ fp16 g_a[(size_t)BQ * HID];                          // act ping (33.5 MB)
__device__ fp16 g_b[(size_t)BQ * HID];                          // act pong
__device__ fp16 g_w_hi[3 * HID * HID], g_w_lo[3 * HID * HID];   // [l][n][k]
__device__ fp16 g_wh_hi[NPAD * HID],   g_wh_lo[NPAD * HID];     // [n][k], zero-padded

// ---------------- helpers ----------------
__device__ __forceinline__ uint32_t s2u(const void* p) {
    return (uint32_t)__cvta_generic_to_shared(p);
}
__device__ __forceinline__ void cp16s(uint32_t dst, const void* src) {
    asm volatile("cp.async.cg.shared.global [%0], [%1], 16;" :: "r"(dst), "l"(src));
}
__device__ __forceinline__ void cp_commit() { asm volatile("cp.async.commit_group;"); }
template <int N> __device__ __forceinline__ void cp_wait() {
    asm volatile("cp.async.wait_group %0;" :: "n"(N));
}
__device__ __forceinline__ void ldsm4(uint32_t& r0, uint32_t& r1, uint32_t& r2, uint32_t& r3,
                                      uint32_t addr) {
    asm volatile("ldmatrix.sync.aligned.m8n8.x4.shared.b16 {%0,%1,%2,%3}, [%4];"
                 : "=r"(r0), "=r"(r1), "=r"(r2), "=r"(r3) : "r"(addr));
}
__device__ __forceinline__ void mma16816(float* d,
                                         uint32_t a0, uint32_t a1, uint32_t a2, uint32_t a3,
                                         uint32_t b0, uint32_t b1) {
    asm volatile(
        "mma.sync.aligned.m16n8k16.row.col.f32.f16.f16.f32 "
        "{%0,%1,%2,%3},{%4,%5,%6,%7},{%8,%9},{%0,%1,%2,%3};"
        : "+f"(d[0]), "+f"(d[1]), "+f"(d[2]), "+f"(d[3])
        : "r"(a0), "r"(a1), "r"(a2), "r"(a3), "r"(b0), "r"(b1));
}
__device__ __forceinline__ float silu(float v) { return v / (1.f + __expf(-v)); }
__device__ __forceinline__ uint32_t sw128(uint32_t o) { return o ^ ((o >> 3) & 0x70); }

// ---------------- weight prep: fp16 hi/lo split, transposed [n][k] ----------------
__global__ void prep_w_hidden(const float* __restrict__ W1, const float* __restrict__ W2,
                              const float* __restrict__ W3) {
    int i = blockIdx.x * 256 + threadIdx.x;
    if (i >= 3 * HID * HID) return;
    int l = i >> 16, rem = i & 65535, n = rem >> 8, k = rem & 255;
    const float* W = (l == 0) ? W1 : (l == 1) ? W2 : W3;
    float v = W[k * HID + n];
    fp16 h = __float2half(v);
    g_w_hi[i] = h;
    g_w_lo[i] = __float2half(v - __half2float(h));
}
__global__ void prep_w_head(const float* __restrict__ Wh) {
    int i = blockIdx.x * 256 + threadIdx.x;
    if (i >= NPAD * HID) return;
    int n = i >> 8, k = i & 255;
    float v = (n < NCOL) ? Wh[k * NCOL + n] : 0.f;
    fp16 h = __float2half(v);
    g_wh_hi[i] = h;
    g_wh_lo[i] = __float2half(v - __half2float(h));
}

// ---------------- layer 0 : silu(x @ W0 + b0), K = 7 ----------------
__global__ __launch_bounds__(256)
void layer0_kernel(const float* __restrict__ x, const float* __restrict__ W0,
                   const float* __restrict__ b0) {
    const int t = threadIdx.x;
    const int row0 = blockIdx.x * 16;
    float w[7];
#pragma unroll
    for (int k = 0; k < 7; k++) w[k] = W0[k * HID + t];
    float bb = b0[t];
    __shared__ float xs[16 * 8];
    for (int i = t; i < 16 * 7; i += 256) {
        int r = i / 7, c = i % 7;
        xs[r * 8 + c] = x[(size_t)(row0 + r) * 7 + c];
    }
    __syncthreads();
#pragma unroll
    for (int r = 0; r < 16; r++) {
        float acc = bb;
#pragma unroll
        for (int k = 0; k < 7; k++) acc += xs[r * 8 + k] * w[k];
        g_a[(size_t)(row0 + r) * HID + t] = __float2half(silu(acc));
    }
}

// ---------------- staging: 3 tiles of 128 rows x 64 fp16, SW128 swizzle ----------------
__device__ __forceinline__ void stage_issue(
    uint32_t sbu, int s, int kc,
    const fp16* __restrict__ A,
    const fp16* __restrict__ Bhi, const fp16* __restrict__ Blo, int t)
{
    const uint32_t st = sbu + s * STAGE_B;
#pragma unroll
    for (int h = 0; h < 4; h++) {
        int ch = t + h * 256;                  // 0..1023
        int r = ch >> 3, c = ch & 7;           // row, 16B chunk
        size_t g = (size_t)r * HID + kc * 64 + c * 8;
        uint32_t sw = sw128((uint32_t)(r * 128 + c * 16));
        cp16s(st + 0 * TILE_B + sw, A + g);
        cp16s(st + 1 * TILE_B + sw, Bhi + g);
        cp16s(st + 2 * TILE_B + sw, Blo + g);
    }
    cp_commit();
}

// ---------------- per-stage compute: 128 MMAs/warp (4 k-steps of 16) ----------------
struct FragOffs {
    uint32_t arow[2];   // [mt]  swizzle-free row base (rows are x16 aligned)
    uint32_t brow[4];   // [np]
    uint32_t kcol[4];   // [kk]  pre-swizzled column term
};

__device__ __forceinline__ void stage_compute(uint32_t sbu, int s,
                                              const FragOffs& fo,
                                              float acc[2][4][2][4])
{
    const uint32_t st = sbu + s * STAGE_B;
#pragma unroll
    for (int kk = 0; kk < 4; kk++) {
        const uint32_t kc = fo.kcol[kk];
        uint32_t a[2][4];
#pragma unroll
        for (int mt = 0; mt < 2; mt++)
            ldsm4(a[mt][0], a[mt][1], a[mt][2], a[mt][3], st + 0 * TILE_B + fo.arow[mt] + kc);
#pragma unroll
        for (int np = 0; np < 4; np++) {
            uint32_t bh4[4], bl4[4];
            ldsm4(bh4[0], bh4[1], bh4[2], bh4[3], st + 1 * TILE_B + fo.brow[np] + kc);
            ldsm4(bl4[0], bl4[1], bl4[2], bl4[3], st + 2 * TILE_B + fo.brow[np] + kc);
            // term-outer ordering: same-acc reuse distance = 4 MMAs
#pragma unroll
            for (int mt = 0; mt < 2; mt++) {
                mma16816(acc[mt][np][0], a[mt][0], a[mt][1], a[mt][2], a[mt][3], bh4[0], bh4[2]);
                mma16816(acc[mt][np][1], a[mt][0], a[mt][1], a[mt][2], a[mt][3], bh4[1], bh4[3]);
            }
#pragma unroll
            for (int mt = 0; mt < 2; mt++) {
                mma16816(acc[mt][np][0], a[mt][0], a[mt][1], a[mt][2], a[mt][3], bl4[0], bl4[2]);
                mma16816(acc[mt][np][1], a[mt][0], a[mt][1], a[mt][2], a[mt][3], bl4[1], bl4[3]);
            }
        }
    }
}

// ---------------- mainloop: 2-stage ring, 4 chunks of K=64, 1 barrier/chunk ----------------
__device__ __forceinline__ void gemm_mainloop(
    uint32_t sbu,
    const fp16* __restrict__ A,
    const fp16* __restrict__ Bhi, const fp16* __restrict__ Blo,
    float acc[2][4][2][4], int t)
{
    const int lane = t & 31, warp = t >> 5, wm = warp & 3, wn = warp >> 2;
    FragOffs fo;
#pragma unroll
    for (int mt = 0; mt < 2; mt++)
        fo.arow[mt] = (uint32_t)((wm * 32 + mt * 16 + (lane & 15)) * 128);
#pragma unroll
    for (int np = 0; np < 4; np++)
        fo.brow[np] = (uint32_t)((wn * 64 + np * 16 + (lane & 15)) * 128);
#pragma unroll
    for (int kk = 0; kk < 4; kk++)
        fo.kcol[kk] = (uint32_t)((kk * 32 + ((lane >> 4) << 4)) ^ ((lane & 7) << 4));

    stage_issue(sbu, 0, 0, A, Bhi, Blo, t);
#pragma unroll
    for (int kc = 0; kc < 4; kc++) {
        cp_wait<0>();
        __syncthreads();
        if (kc < 3)
            stage_issue(sbu, (kc + 1) & 1, kc + 1, A, Bhi, Blo, t);
        stage_compute(sbu, kc & 1, fo, acc);
    }
}

// ---------------- hidden GEMM ----------------
template <int L>
__global__ __launch_bounds__(256, 2)
void gemm_hidden(const float* __restrict__ bias) {
    extern __shared__ __align__(16) char sm[];
    const uint32_t sbu = s2u(sm);

    const int t    = threadIdx.x;
    const int row0 = blockIdx.y * 128;
    const int nb0  = blockIdx.x * 128;

    const fp16* A = (L == 1 ? g_b : g_a) + (size_t)row0 * HID;
    fp16* O = (L == 1) ? g_a : g_b;
    const fp16* Bhi = g_w_hi + (size_t)L * HID * HID + (size_t)nb0 * HID;
    const fp16* Blo = g_w_lo + (size_t)L * HID * HID + (size_t)nb0 * HID;

    float acc[2][4][2][4];
#pragma unroll
    for (int a = 0; a < 2; a++)
#pragma unroll
        for (int b = 0; b < 4; b++)
#pragma unroll
            for (int c = 0; c < 2; c++)
#pragma unroll
                for (int d = 0; d < 4; d++) acc[a][b][c][d] = 0.f;

    gemm_mainloop(sbu, A, Bhi, Blo, acc, t);

    const int lane = t & 31, warp = t >> 5, wm = warp & 3, wn = warp >> 2;
#pragma unroll
    for (int mt = 0; mt < 2; mt++) {
#pragma unroll
        for (int np = 0; np < 4; np++) {
#pragma unroll
            for (int sub = 0; sub < 2; sub++) {
                float* d = acc[mt][np][sub];
                int col = nb0 + wn * 64 + np * 16 + sub * 8 + (lane & 3) * 2;
                int r   = row0 + wm * 32 + mt * 16 + (lane >> 2);
                float bb0 = bias[col], bb1 = bias[col + 1];
                __half2 v0; v0.x = __float2half(silu(d[0] + bb0));
                            v0.y = __float2half(silu(d[1] + bb1));
                *(__half2*)(O + (size_t)r * HID + col) = v0;
                __half2 v1; v1.x = __float2half(silu(d[2] + bb0));
                            v1.y = __float2half(silu(d[3] + bb1));
                *(__half2*)(O + (size_t)(r + 8) * HID + col) = v1;
            }
        }
    }
}

// ---------------- head GEMM ----------------
__global__ __launch_bounds__(256, 2)
void gemm_head(const float* __restrict__ x, const float* __restrict__ bh,
               float* __restrict__ out) {
    extern __shared__ __align__(16) char sm[];
    const uint32_t sbu = s2u(sm);
    __shared__ float sL[128], sR[128], sN[128];

    const int t    = threadIdx.x;
    const int row0 = blockIdx.y * 128;
    const int nb0  = blockIdx.x * 128;

    if (t < 128) {
        float lam = x[(size_t)(row0 + t) * 7];
        float s   = 1.f / (1.f + __expf(-lam * (5.0f / 0.15f)));
        sL[t] = 1.f - s;
        sR[t] = s;
        sN[t] = __expf(-25.f * lam * lam);
    }

    const fp16* A   = g_b + (size_t)row0 * HID;
    const fp16* Bhi = g_wh_hi + (size_t)nb0 * HID;
    const fp16* Blo = g_wh_lo + (size_t)nb0 * HID;

    float acc[2][4][2][4];
#pragma unroll
    for (int a = 0; a < 2; a++)
#pragma unroll
        for (int b = 0; b < 4; b++)
#pragma unroll
            for (int c = 0; c < 2; c++)
#pragma unroll
                for (int d = 0; d < 4; d++) acc[a][b][c][d] = 0.f;

    gemm_mainloop(sbu, A, Bhi, Blo, acc, t);

    const int lane = t & 31, warp = t >> 5, wm = warp & 3, wn = warp >> 2;
#pragma unroll
    for (int mt = 0; mt < 2; mt++) {
#pragma unroll
        for (int np = 0; np < 4; np++) {
#pragma unroll
            for (int sub = 0; sub < 2; sub++) {
                float* d = acc[mt][np][sub];
                int col = nb0 + wn * 64 + np * 16 + sub * 8 + (lane & 3) * 2;
                int rl  = wm * 32 + mt * 16 + (lane >> 2);
                int rg  = row0 + rl;
                if (col < NCOL) {
                    float bb = bh[col];
                    int   h  = col / 35;
                    float s0 = (h < 35) ? 1.f : (h < 49) ? sL[rl]     : (h < 63) ? sR[rl]     : sN[rl];
                    float s1 = (h < 35) ? 1.f : (h < 49) ? sL[rl + 8] : (h < 63) ? sR[rl + 8] : sN[rl + 8];
                    out[(size_t)rg * NCOL + col]       = (d[0] + bb) * s0;
                    out[(size_t)(rg + 8) * NCOL + col] = (d[2] + bb) * s1;
                }
                int col1 = col + 1;
                if (col1 < NCOL) {
                    float bb = bh[col1];
                    int   h  = col1 / 35;
                    float s0 = (h < 35) ? 1.f : (h < 49) ? sL[rl]     : (h < 63) ? sR[rl]     : sN[rl];
                    float s1 = (h < 35) ? 1.f : (h < 49) ? sL[rl + 8] : (h < 63) ? sR[rl + 8] : sN[rl + 8];
                    out[(size_t)rg * NCOL + col1]       = (d[1] + bb) * s0;
                    out[(size_t)(rg + 8) * NCOL + col1] = (d[3] + bb) * s1;
                }
            }
        }
    }
}

// ---------------- launch ----------------
extern "C" void kernel_launch(void* const* d_in, const int* in_sizes, int n_in,
                              void* d_out, int out_size) {
    const float* x  = (const float*)d_in[0];
    const float* W0 = (const float*)d_in[1];
    const float* b0 = (const float*)d_in[2];
    const float* W1 = (const float*)d_in[3];
    const float* b1 = (const float*)d_in[4];
    const float* W2 = (const float*)d_in[5];
    const float* b2 = (const float*)d_in[6];
    const float* W3 = (const float*)d_in[7];
    const float* b3 = (const float*)d_in[8];
    const float* Wh = (const float*)d_in[9];
    const float* bh = (const float*)d_in[10];
    float* out = (float*)d_out;

    static bool attr_done = false;
    if (!attr_done) {
        cudaFuncSetAttribute(gemm_hidden<0>, cudaFuncAttributeMaxDynamicSharedMemorySize, DYN_BYTES);
        cudaFuncSetAttribute(gemm_hidden<1>, cudaFuncAttributeMaxDynamicSharedMemorySize, DYN_BYTES);
        cudaFuncSetAttribute(gemm_hidden<2>, cudaFuncAttributeMaxDynamicSharedMemorySize, DYN_BYTES);
        cudaFuncSetAttribute(gemm_head,      cudaFuncAttributeMaxDynamicSharedMemorySize, DYN_BYTES);
        attr_done = true;
    }

    prep_w_hidden<<<(3 * HID * HID + 255) / 256, 256>>>(W1, W2, W3);
    prep_w_head<<<(NPAD * HID + 255) / 256, 256>>>(Wh);
    layer0_kernel<<<BQ / 16, 256>>>(x, W0, b0);

    dim3 gh(HID / 128, BQ / 128);        // (2, 512)
    gemm_hidden<0><<<gh, 256, DYN_BYTES>>>(b1);   // a -> b
    gemm_hidden<1><<<gh, 256, DYN_BYTES>>>(b2);   // b -> a
    gemm_hidden<2><<<gh, 256, DYN_BYTES>>>(b3);   // a -> b

    dim3 gd(NPAD / 128, BQ / 128);       // (22, 512)
    gemm_head<<<gd, 256, DYN_BYTES>>>(x, bh, out);
}

// round 12
// speedup vs baseline: 1.7843x; 1.7843x over previous
#include <cuda_runtime.h>
#include <cuda_fp16.h>
#include <cstdint>

#define BQ   65536
#define HID  256
#define NCOL 2695
#define NPAD 2816                 // 22 * 128
#define TILE_B  8192              // 128 rows x 64B (32 fp16 of k), SW64-swizzled
#define STAGE_B (2 * TILE_B)      // A, B = 16 KB
#define NSTAGE  6
#define DYN_BYTES (NSTAGE * STAGE_B)   // 96 KB

typedef __half fp16;

// ---------------- scratch ----------------
__device__ fp16 g_a[(size_t)BQ * HID];                      // act ping (33.5 MB)
__device__ fp16 g_b[(size_t)BQ * HID];                      // act pong
__device__ fp16 g_w[3 * HID * HID];                         // W1..W3, [l][n][k]
__device__ fp16 g_wh[NPAD * HID];                           // Wh, [n][k], zero-padded

// ---------------- helpers ----------------
__device__ __forceinline__ uint32_t s2u(const void* p) {
    return (uint32_t)__cvta_generic_to_shared(p);
}
__device__ __forceinline__ void cp16s(uint32_t dst, const void* src) {
    asm volatile("cp.async.cg.shared.global [%0], [%1], 16;" :: "r"(dst), "l"(src));
}
__device__ __forceinline__ void cp_commit() { asm volatile("cp.async.commit_group;"); }
template <int N> __device__ __forceinline__ void cp_wait() {
    asm volatile("cp.async.wait_group %0;" :: "n"(N));
}
__device__ __forceinline__ void ldsm4(uint32_t& r0, uint32_t& r1, uint32_t& r2, uint32_t& r3,
                                      uint32_t addr) {
    asm volatile("ldmatrix.sync.aligned.m8n8.x4.shared.b16 {%0,%1,%2,%3}, [%4];"
                 : "=r"(r0), "=r"(r1), "=r"(r2), "=r"(r3) : "r"(addr));
}
__device__ __forceinline__ void mma16816(float* d,
                                         uint32_t a0, uint32_t a1, uint32_t a2, uint32_t a3,
                                         uint32_t b0, uint32_t b1) {
    asm volatile(
        "mma.sync.aligned.m16n8k16.row.col.f32.f16.f16.f32 "
        "{%0,%1,%2,%3},{%4,%5,%6,%7},{%8,%9},{%0,%1,%2,%3};"
        : "+f"(d[0]), "+f"(d[1]), "+f"(d[2]), "+f"(d[3])
        : "r"(a0), "r"(a1), "r"(a2), "r"(a3), "r"(b0), "r"(b1));
}
__device__ __forceinline__ float silu(float v) { return v / (1.f + __expf(-v)); }
__device__ __forceinline__ uint32_t sw64(uint32_t o) { return o ^ ((o >> 3) & 0x30); }

// ---------------- weight prep: fp16, transposed [n][k] ----------------
__global__ void prep_w_hidden(const float* __restrict__ W1, const float* __restrict__ W2,
                              const float* __restrict__ W3) {
    int i = blockIdx.x * 256 + threadIdx.x;
    if (i >= 3 * HID * HID) return;
    int l = i >> 16, rem = i & 65535, n = rem >> 8, k = rem & 255;
    const float* W = (l == 0) ? W1 : (l == 1) ? W2 : W3;
    g_w[i] = __float2half(W[k * HID + n]);
}
__global__ void prep_w_head(const float* __restrict__ Wh) {
    int i = blockIdx.x * 256 + threadIdx.x;
    if (i >= NPAD * HID) return;
    int n = i >> 8, k = i & 255;
    g_wh[i] = __float2half((n < NCOL) ? Wh[k * NCOL + n] : 0.f);
}

// ---------------- layer 0 : silu(x @ W0 + b0), K = 7 ----------------
__global__ __launch_bounds__(256)
void layer0_kernel(const float* __restrict__ x, const float* __restrict__ W0,
                   const float* __restrict__ b0) {
    const int t = threadIdx.x;
    const int row0 = blockIdx.x * 16;
    float w[7];
#pragma unroll
    for (int k = 0; k < 7; k++) w[k] = W0[k * HID + t];
    float bb = b0[t];
    __shared__ float xs[16 * 8];
    for (int i = t; i < 16 * 7; i += 256) {
        int r = i / 7, c = i % 7;
        xs[r * 8 + c] = x[(size_t)(row0 + r) * 7 + c];
    }
    __syncthreads();
#pragma unroll
    for (int r = 0; r < 16; r++) {
        float acc = bb;
#pragma unroll
        for (int k = 0; k < 7; k++) acc += xs[r * 8 + k] * w[k];
        g_a[(size_t)(row0 + r) * HID + t] = __float2half(silu(acc));
    }
}

// ---------------- staging: 2 tiles of 128 rows x 32 fp16, SW64 swizzle ----------------
__device__ __forceinline__ void stage_issue(
    uint32_t sbu, int s, int kc,
    const fp16* __restrict__ A, const fp16* __restrict__ B, int t)
{
    const uint32_t st = sbu + s * STAGE_B;
#pragma unroll
    for (int h = 0; h < 2; h++) {
        int ch = t + h * 256;                  // 0..511
        int r = ch >> 2, c = ch & 3;           // row, 16B chunk
        size_t g = (size_t)r * HID + kc * 32 + c * 8;
        uint32_t sw = sw64((uint32_t)(r * 64 + c * 16));
        cp16s(st + 0 * TILE_B + sw, A + g);
        cp16s(st + 1 * TILE_B + sw, B + g);
    }
    cp_commit();
}

// ---------------- per-stage compute: 32 MMAs/warp ----------------
struct FragOffs {
    uint32_t a[2][2];   // [kk][mt]
    uint32_t b[2][4];   // [kk][np]
};

__device__ __forceinline__ void stage_compute(uint32_t sbu, int s,
                                              const FragOffs& fo,
                                              float acc[2][4][2][4])
{
    const uint32_t st = sbu + s * STAGE_B;
#pragma unroll
    for (int kk = 0; kk < 2; kk++) {
        uint32_t a[2][4];
#pragma unroll
        for (int mt = 0; mt < 2; mt++)
            ldsm4(a[mt][0], a[mt][1], a[mt][2], a[mt][3], st + 0 * TILE_B + fo.a[kk][mt]);
#pragma unroll
        for (int np = 0; np < 4; np++) {
            uint32_t b4[4];
            ldsm4(b4[0], b4[1], b4[2], b4[3], st + 1 * TILE_B + fo.b[kk][np]);
#pragma unroll
            for (int mt = 0; mt < 2; mt++) {
                mma16816(acc[mt][np][0], a[mt][0], a[mt][1], a[mt][2], a[mt][3], b4[0], b4[2]);
                mma16816(acc[mt][np][1], a[mt][0], a[mt][1], a[mt][2], a[mt][3], b4[1], b4[3]);
            }
        }
    }
}

// ---------------- mainloop: 6-stage ring, 8 chunks, barrier per 2 chunks ----------------
__device__ __forceinline__ void gemm_mainloop(
    uint32_t sbu,
    const fp16* __restrict__ A, const fp16* __restrict__ B,
    float acc[2][4][2][4], int t)
{
    const int lane = t & 31, warp = t >> 5, wm = warp & 3, wn = warp >> 2;
    FragOffs fo;
#pragma unroll
    for (int kk = 0; kk < 2; kk++) {
        uint32_t kb = kk * 32 + ((lane >> 4) << 4);
#pragma unroll
        for (int mt = 0; mt < 2; mt++)
            fo.a[kk][mt] = sw64((uint32_t)((wm * 32 + mt * 16 + (lane & 15)) * 64) + kb);
#pragma unroll
        for (int np = 0; np < 4; np++)
            fo.b[kk][np] = sw64((uint32_t)((wn * 64 + np * 16 + (lane & 15)) * 64) + kb);
    }

    // preload chunks 0..3 into stages 0..3
    stage_issue(sbu, 0, 0, A, B, t);
    stage_issue(sbu, 1, 1, A, B, t);
    stage_issue(sbu, 2, 2, A, B, t);
    stage_issue(sbu, 3, 3, A, B, t);

#pragma unroll
    for (int p = 0; p < 4; p++) {                 // 2 chunks per barrier
        if (p < 3) cp_wait<2>(); else cp_wait<0>();
        __syncthreads();
        if (p < 2) {                              // chunks 4..7 -> stages 4,5,0,1
            stage_issue(sbu, (2 * p + 4) % NSTAGE, 2 * p + 4, A, B, t);
            stage_issue(sbu, (2 * p + 5) % NSTAGE, 2 * p + 5, A, B, t);
        }
        stage_compute(sbu, (2 * p) % NSTAGE, fo, acc);
        stage_compute(sbu, (2 * p + 1) % NSTAGE, fo, acc);
    }
}

// ---------------- hidden GEMM ----------------
template <int L>
__global__ __launch_bounds__(256, 2)
void gemm_hidden(const float* __restrict__ bias) {
    extern __shared__ __align__(16) char sm[];
    const uint32_t sbu = s2u(sm);

    const int t    = threadIdx.x;
    const int row0 = blockIdx.y * 128;
    const int nb0  = blockIdx.x * 128;

    const fp16* A = (L == 1 ? g_b : g_a) + (size_t)row0 * HID;
    fp16* O = (L == 1) ? g_a : g_b;
    const fp16* B = g_w + (size_t)L * HID * HID + (size_t)nb0 * HID;

    float acc[2][4][2][4];
#pragma unroll
    for (int a = 0; a < 2; a++)
#pragma unroll
        for (int b = 0; b < 4; b++)
#pragma unroll
            for (int c = 0; c < 2; c++)
#pragma unroll
                for (int d = 0; d < 4; d++) acc[a][b][c][d] = 0.f;

    gemm_mainloop(sbu, A, B, acc, t);

    const int lane = t & 31, warp = t >> 5, wm = warp & 3, wn = warp >> 2;
#pragma unroll
    for (int mt = 0; mt < 2; mt++) {
#pragma unroll
        for (int np = 0; np < 4; np++) {
#pragma unroll
            for (int sub = 0; sub < 2; sub++) {
                float* d = acc[mt][np][sub];
                int col = nb0 + wn * 64 + np * 16 + sub * 8 + (lane & 3) * 2;
                int r   = row0 + wm * 32 + mt * 16 + (lane >> 2);
                float bb0 = bias[col], bb1 = bias[col + 1];
                __half2 v0; v0.x = __float2half(silu(d[0] + bb0));
                            v0.y = __float2half(silu(d[1] + bb1));
                *(__half2*)(O + (size_t)r * HID + col) = v0;
                __half2 v1; v1.x = __float2half(silu(d[2] + bb0));
                            v1.y = __float2half(silu(d[3] + bb1));
                *(__half2*)(O + (size_t)(r + 8) * HID + col) = v1;
            }
        }
    }
}

// ---------------- head GEMM ----------------
__global__ __launch_bounds__(256, 2)
void gemm_head(const float* __restrict__ x, const float* __restrict__ bh,
               float* __restrict__ out) {
    extern __shared__ __align__(16) char sm[];
    const uint32_t sbu = s2u(sm);
    __shared__ float sL[128], sR[128], sN[128];

    const int t    = threadIdx.x;
    const int row0 = blockIdx.y * 128;
    const int nb0  = blockIdx.x * 128;

    if (t < 128) {
        float lam = x[(size_t)(row0 + t) * 7];
        float s   = 1.f / (1.f + __expf(-lam * (5.0f / 0.15f)));
        sL[t] = 1.f - s;
        sR[t] = s;
        sN[t] = __expf(-25.f * lam * lam);
    }

    const fp16* A = g_b + (size_t)row0 * HID;
    const fp16* B = g_wh + (size_t)nb0 * HID;

    float acc[2][4][2][4];
#pragma unroll
    for (int a = 0; a < 2; a++)
#pragma unroll
        for (int b = 0; b < 4; b++)
#pragma unroll
            for (int c = 0; c < 2; c++)
#pragma unroll
                for (int d = 0; d < 4; d++) acc[a][b][c][d] = 0.f;

    gemm_mainloop(sbu, A, B, acc, t);

    const int lane = t & 31, warp = t >> 5, wm = warp & 3, wn = warp >> 2;
#pragma unroll
    for (int mt = 0; mt < 2; mt++) {
#pragma unroll
        for (int np = 0; np < 4; np++) {
#pragma unroll
            for (int sub = 0; sub < 2; sub++) {
                float* d = acc[mt][np][sub];
                int col = nb0 + wn * 64 + np * 16 + sub * 8 + (lane & 3) * 2;
                int rl  = wm * 32 + mt * 16 + (lane >> 2);
                int rg  = row0 + rl;
                if (col < NCOL) {
                    float bb = bh[col];
                    int   h  = col / 35;
                    float s0 = (h < 35) ? 1.f : (h < 49) ? sL[rl]     : (h < 63) ? sR[rl]     : sN[rl];
                    float s1 = (h < 35) ? 1.f : (h < 49) ? sL[rl + 8] : (h < 63) ? sR[rl + 8] : sN[rl + 8];
                    out[(size_t)rg * NCOL + col]       = (d[0] + bb) * s0;
                    out[(size_t)(rg + 8) * NCOL + col] = (d[2] + bb) * s1;
                }
                int col1 = col + 1;
                if (col1 < NCOL) {
                    float bb = bh[col1];
                    int   h  = col1 / 35;
                    float s0 = (h < 35) ? 1.f : (h < 49) ? sL[rl]     : (h < 63) ? sR[rl]     : sN[rl];
                    float s1 = (h < 35) ? 1.f : (h < 49) ? sL[rl + 8] : (h < 63) ? sR[rl + 8] : sN[rl + 8];
                    out[(size_t)rg * NCOL + col1]       = (d[1] + bb) * s0;
                    out[(size_t)(rg + 8) * NCOL + col1] = (d[3] + bb) * s1;
                }
            }
        }
    }
}

// ---------------- launch ----------------
extern "C" void kernel_launch(void* const* d_in, const int* in_sizes, int n_in,
                              void* d_out, int out_size) {
    const float* x  = (const float*)d_in[0];
    const float* W0 = (const float*)d_in[1];
    const float* b0 = (const float*)d_in[2];
    const float* W1 = (const float*)d_in[3];
    const float* b1 = (const float*)d_in[4];
    const float* W2 = (const float*)d_in[5];
    const float* b2 = (const float*)d_in[6];
    const float* W3 = (const float*)d_in[7];
    const float* b3 = (const float*)d_in[8];
    const float* Wh = (const float*)d_in[9];
    const float* bh = (const float*)d_in[10];
    float* out = (float*)d_out;

    static bool attr_done = false;
    if (!attr_done) {
        cudaFuncSetAttribute(gemm_hidden<0>, cudaFuncAttributeMaxDynamicSharedMemorySize, DYN_BYTES);
        cudaFuncSetAttribute(gemm_hidden<1>, cudaFuncAttributeMaxDynamicSharedMemorySize, DYN_BYTES);
        cudaFuncSetAttribute(gemm_hidden<2>, cudaFuncAttributeMaxDynamicSharedMemorySize, DYN_BYTES);
        cudaFuncSetAttribute(gemm_head,      cudaFuncAttributeMaxDynamicSharedMemorySize, DYN_BYTES);
        attr_done = true;
    }

    prep_w_hidden<<<(3 * HID * HID + 255) / 256, 256>>>(W1, W2, W3);
    prep_w_head<<<(NPAD * HID + 255) / 256, 256>>>(Wh);
    layer0_kernel<<<BQ / 16, 256>>>(x, W0, b0);

    dim3 gh(HID / 128, BQ / 128);        // (2, 512)
    gemm_hidden<0><<<gh, 256, DYN_BYTES>>>(b1);   // a -> b
    gemm_hidden<1><<<gh, 256, DYN_BYTES>>>(b2);   // b -> a
    gemm_hidden<2><<<gh, 256, DYN_BYTES>>>(b3);   // a -> b

    dim3 gd(NPAD / 128, BQ / 128);       // (22, 512)
    gemm_head<<<gd, 256, DYN_BYTES>>>(x, bh, out);
}